// round 1
// baseline (speedup 1.0000x reference)
#include <cuda_runtime.h>
#include <cuda_bf16.h>
#include <mma.h>
#include <math.h>

using namespace nvcuda;

#define FEAT    256
#define NMOL    1024
#define TM      128          // atoms per block tile
#define NTHREADS 512         // 16 warps: 4 (M) x 4 (N)

__device__ __constant__ float kScale = 5.992277830325989f;
__device__ __constant__ float kShift = -406274.63784969115f;

// bf16 weight copies (pre-converted once per launch; L2-resident afterwards)
__device__ __nv_bfloat16 g_W1[FEAT * FEAT];
__device__ __nv_bfloat16 g_W2[FEAT * FEAT];
__device__ __nv_bfloat16 g_W3[FEAT];
__device__ int g_is64;

// ---------------------------------------------------------------------------
// Kernel 1: convert fp32 weights -> bf16 device globals
// ---------------------------------------------------------------------------
__global__ void convert_weights(const float* __restrict__ W1,
                                const float* __restrict__ W2,
                                const float* __restrict__ W3) {
    int i = blockIdx.x * blockDim.x + threadIdx.x;
    if (i < FEAT * FEAT) {
        g_W1[i] = __float2bfloat16(W1[i]);
        g_W2[i] = __float2bfloat16(W2[i]);
    }
    if (i < FEAT) g_W3[i] = __float2bfloat16(W3[i]);
}

// ---------------------------------------------------------------------------
// Kernel 2: init output to SHIFT, detect batch dtype (int32 vs int64)
// ---------------------------------------------------------------------------
__global__ void init_out(const void* __restrict__ batch, float* __restrict__ out) {
    int i = blockIdx.x * blockDim.x + threadIdx.x;
    if (i < NMOL) out[i] = kShift;
    if (i == 0) {
        // int64 little-endian layout: 32-bit words alternate [value, 0].
        // Probe mid-array where mol ids are guaranteed > 0 in either layout.
        const int* w = (const int*)batch;
        g_is64 = (w[1001] == 0 && w[1000] > 0) ? 1 : 0;
    }
}

__device__ __forceinline__ int load_mol(const void* batch, int i) {
    if (g_is64) return (int)((const long long*)batch)[i];
    return ((const int*)batch)[i];
}

// ---------------------------------------------------------------------------
// Fused 3-layer MLP + segment-sum pooling
// ---------------------------------------------------------------------------
struct SmemLayout {
    __nv_bfloat16 A[TM * FEAT];   // 64 KB  : bf16 activations (input of current GEMM)
    float         Fb[TM * FEAT];  // 128 KB : fp32 GEMM accum staging
    float         molacc[NMOL];   // 4 KB   : per-block molecule partial sums
};

// One GEMM layer: S->A [TM,256] bf16 (row-major, ld=256)  x  W [256,256] bf16
// (row-major, ld=256)  ->  S->Fb fp32.
__device__ __forceinline__ void gemm_layer(SmemLayout* S, const __nv_bfloat16* __restrict__ W) {
    int warp = threadIdx.x >> 5;
    int wm = warp >> 2;        // 0..3 : 32-row strip
    int wn = warp & 3;         // 0..3 : 64-col strip

    wmma::fragment<wmma::accumulator, 16, 16, 16, float> c[2][4];
#pragma unroll
    for (int im = 0; im < 2; im++)
#pragma unroll
        for (int in_ = 0; in_ < 4; in_++)
            wmma::fill_fragment(c[im][in_], 0.0f);

    const __nv_bfloat16* Abase = S->A + (wm * 32) * FEAT;
    const __nv_bfloat16* Wbase = W + wn * 64;

#pragma unroll
    for (int k = 0; k < FEAT; k += 16) {
        wmma::fragment<wmma::matrix_a, 16, 16, 16, __nv_bfloat16, wmma::row_major> a0, a1;
        wmma::load_matrix_sync(a0, Abase + k, FEAT);
        wmma::load_matrix_sync(a1, Abase + 16 * FEAT + k, FEAT);
#pragma unroll
        for (int in_ = 0; in_ < 4; in_++) {
            wmma::fragment<wmma::matrix_b, 16, 16, 16, __nv_bfloat16, wmma::row_major> b;
            wmma::load_matrix_sync(b, Wbase + k * FEAT + in_ * 16, FEAT);
            wmma::mma_sync(c[0][in_], a0, b, c[0][in_]);
            wmma::mma_sync(c[1][in_], a1, b, c[1][in_]);
        }
    }

#pragma unroll
    for (int im = 0; im < 2; im++)
#pragma unroll
        for (int in_ = 0; in_ < 4; in_++)
            wmma::store_matrix_sync(&S->Fb[(wm * 32 + im * 16) * FEAT + wn * 64 + in_ * 16],
                                    c[im][in_], FEAT, wmma::mem_row_major);
}

__device__ __forceinline__ void bias_silu(SmemLayout* S, const float* __restrict__ bias) {
    for (int idx = threadIdx.x; idx < TM * FEAT; idx += NTHREADS) {
        float v = S->Fb[idx] + bias[idx & (FEAT - 1)];
        float s = v * (1.0f / (1.0f + __expf(-v)));
        S->A[idx] = __float2bfloat16(s);
    }
}

__global__ void __launch_bounds__(NTHREADS, 1)
fused_mlp(const float* __restrict__ X, const void* __restrict__ batch,
          const float* __restrict__ b1, const float* __restrict__ b2,
          const float* __restrict__ b3, float* __restrict__ out, int n_atoms) {
    extern __shared__ char sraw[];
    SmemLayout* S = (SmemLayout*)sraw;
    const int tid = threadIdx.x;
    const int row0 = blockIdx.x * TM;

    // zero per-block molecule accumulator
    for (int i = tid; i < NMOL; i += NTHREADS) S->molacc[i] = 0.0f;

    // load X tile fp32 -> bf16 smem (vectorized float4; zero-fill tail rows)
    for (int idx = tid * 4; idx < TM * FEAT; idx += NTHREADS * 4) {
        int r = idx >> 8;                 // /256
        int grow = row0 + r;
        float4 v;
        if (grow < n_atoms)
            v = *(const float4*)(X + (long long)grow * FEAT + (idx & (FEAT - 1)));
        else
            v = make_float4(0.f, 0.f, 0.f, 0.f);
        __nv_bfloat16* dst = S->A + idx;
        dst[0] = __float2bfloat16(v.x);
        dst[1] = __float2bfloat16(v.y);
        dst[2] = __float2bfloat16(v.z);
        dst[3] = __float2bfloat16(v.w);
    }
    __syncthreads();

    // layer 1
    gemm_layer(S, g_W1);
    __syncthreads();
    bias_silu(S, b1);
    __syncthreads();

    // layer 2
    gemm_layer(S, g_W2);
    __syncthreads();
    bias_silu(S, b2);
    __syncthreads();

    // layer 3 (GEMV per row) + pooling
    const int warp = tid >> 5, lane = tid & 31;
    const float b3v = *b3;
#pragma unroll
    for (int rr = 0; rr < TM / 16 /*8 rows per warp*/; rr++) {
        int r = warp * 8 + rr;
        float sum = 0.0f;
#pragma unroll
        for (int j = 0; j < FEAT / 32; j++) {
            int k = lane + j * 32;
            sum += __bfloat162float(S->A[r * FEAT + k]) * __bfloat162float(g_W3[k]);
        }
#pragma unroll
        for (int o = 16; o > 0; o >>= 1)
            sum += __shfl_xor_sync(0xffffffffu, sum, o);
        int grow = row0 + r;
        if (lane == 0 && grow < n_atoms) {
            int mol = load_mol(batch, grow);
            atomicAdd(&S->molacc[mol], sum + b3v);
        }
    }
    __syncthreads();

    // flush non-zero molecule sums to global (skipping exact zeros is safe: +0)
    for (int i = tid; i < NMOL; i += NTHREADS) {
        float v = S->molacc[i];
        if (v != 0.0f) atomicAdd(out + i, v * kScale);
    }
}

// ---------------------------------------------------------------------------
// Launch
// ---------------------------------------------------------------------------
extern "C" void kernel_launch(void* const* d_in, const int* in_sizes, int n_in,
                              void* d_out, int out_size) {
    const float* atom_node = (const float*)d_in[0];
    const void*  batch     = d_in[1];
    const float* W1 = (const float*)d_in[2];
    const float* b1 = (const float*)d_in[3];
    const float* W2 = (const float*)d_in[4];
    const float* b2 = (const float*)d_in[5];
    const float* W3 = (const float*)d_in[6];
    const float* b3 = (const float*)d_in[7];
    float* out = (float*)d_out;

    const int n_atoms = in_sizes[1];  // batch element count

    // weights -> bf16 device globals
    convert_weights<<<(FEAT * FEAT + 255) / 256, 256>>>(W1, W2, W3);

    // init output + batch dtype detection
    init_out<<<(NMOL + 255) / 256, 256>>>(batch, out);

    // fused MLP + pooling
    const int smem_bytes = (int)sizeof(SmemLayout);
    cudaFuncSetAttribute(fused_mlp, cudaFuncAttributeMaxDynamicSharedMemorySize, smem_bytes);
    int blocks = (n_atoms + TM - 1) / TM;
    fused_mlp<<<blocks, NTHREADS, smem_bytes>>>(atom_node, batch, b1, b2, b3, out, n_atoms);
}

// round 3
// speedup vs baseline: 2.6866x; 2.6866x over previous
#include <cuda_runtime.h>
#include <cuda_bf16.h>
#include <math.h>
#include <stdint.h>

#define FEAT     256
#define NMOL     1024
#define TM       128
#define NTHREADS 512           // 16 warps: 4 (M) x 4 (N)
#define LDA      264           // padded bf16 row stride (528 B)
#define LDA_B    (LDA * 2)
#define W_BYTES  (FEAT * LDA * 2)   // 135168
#define A_BYTES  (TM * LDA * 2)     // 67584

__device__ __constant__ float kScale = 5.992277830325989f;
__device__ __constant__ float kShift = -406274.63784969115f;

// padded bf16 weight images: img[k*LDA + n] = W[k][n]
__device__ __align__(128) __nv_bfloat16 g_W1img[FEAT * LDA];
__device__ __align__(128) __nv_bfloat16 g_W2img[FEAT * LDA];
__device__ int g_is64;

// ---------------------------------------------------------------------------
// PTX helpers (base sm_90 features only — no 'a'-gated instructions)
// ---------------------------------------------------------------------------
__device__ __forceinline__ uint32_t smem_u32(const void* p) {
    uint32_t a;
    asm("{ .reg .u64 t; cvta.to.shared.u64 t, %1; cvt.u32.u64 %0, t; }" : "=r"(a) : "l"(p));
    return a;
}
#define MBARRIER_INIT(addr, cnt) \
    asm volatile("mbarrier.init.shared.b64 [%0], %1;" :: "r"(addr), "r"(cnt) : "memory")
#define MBARRIER_EXPECT_TX(addr, bytes) \
    asm volatile("mbarrier.arrive.expect_tx.shared.b64 _, [%0], %1;" :: "r"(addr), "r"(bytes) : "memory")
#define MBARRIER_WAIT_PARITY(addr, ph) do { \
    uint32_t _m = (addr); uint32_t _p = (ph); uint32_t _d; \
    asm volatile("{ .reg .pred p; mbarrier.try_wait.parity.acquire.cta.shared::cta.b64 p, [%1], %2; selp.b32 %0,1,0,p; }" \
        : "=r"(_d) : "r"(_m), "r"(_p) : "memory"); \
    if (!_d) { asm volatile("{ .reg .pred P1; WL_%=: mbarrier.try_wait.parity.acquire.cta.shared::cta.b64 P1, [%0], %1, 0x989680; @P1 bra.uni WD_%=; bra.uni WL_%=; WD_%=: }" \
        :: "r"(_m), "r"(_p) : "memory"); } \
} while (0)
#define FENCE_PROXY_ASYNC() asm volatile("fence.proxy.async.shared::cta;" ::: "memory")

__device__ __forceinline__ void bulk_g2s(uint32_t dst, const void* src, uint32_t bytes, uint32_t mbar) {
    asm volatile("cp.async.bulk.shared::cta.global.mbarrier::complete_tx::bytes [%0], [%1], %2, [%3];"
                 :: "r"(dst), "l"(src), "r"(bytes), "r"(mbar) : "memory");
}
__device__ __forceinline__ void ldsm_x4(uint32_t* r, uint32_t addr) {
    asm volatile("ldmatrix.sync.aligned.m8n8.x4.shared.b16 {%0,%1,%2,%3}, [%4];"
                 : "=r"(r[0]), "=r"(r[1]), "=r"(r[2]), "=r"(r[3]) : "r"(addr));
}
__device__ __forceinline__ void ldsm_x4_t(uint32_t* r, uint32_t addr) {
    asm volatile("ldmatrix.sync.aligned.m8n8.x4.trans.shared.b16 {%0,%1,%2,%3}, [%4];"
                 : "=r"(r[0]), "=r"(r[1]), "=r"(r[2]), "=r"(r[3]) : "r"(addr));
}
__device__ __forceinline__ void mma16816(float* c, const uint32_t* a, uint32_t b0, uint32_t b1) {
    asm volatile("mma.sync.aligned.m16n8k16.row.col.f32.bf16.bf16.f32 "
                 "{%0,%1,%2,%3}, {%4,%5,%6,%7}, {%8,%9}, {%0,%1,%2,%3};"
                 : "+f"(c[0]), "+f"(c[1]), "+f"(c[2]), "+f"(c[3])
                 : "r"(a[0]), "r"(a[1]), "r"(a[2]), "r"(a[3]), "r"(b0), "r"(b1));
}
__device__ __forceinline__ float silu(float v) { return v * (1.0f / (1.0f + __expf(-v))); }

// ---------------------------------------------------------------------------
// One-time: fp32 W -> padded bf16 images
// ---------------------------------------------------------------------------
__global__ void convert_weights(const float* __restrict__ W1, const float* __restrict__ W2) {
    int i = blockIdx.x * blockDim.x + threadIdx.x;
    if (i < FEAT * FEAT) {
        int k = i >> 8, n = i & 255;
        g_W1img[k * LDA + n] = __float2bfloat16(W1[i]);
        g_W2img[k * LDA + n] = __float2bfloat16(W2[i]);
    }
}

__global__ void init_out(const void* __restrict__ batch, float* __restrict__ out) {
    int i = blockIdx.x * blockDim.x + threadIdx.x;
    if (i < NMOL) out[i] = kShift;
    if (i == 0) {
        const int* w = (const int*)batch;
        g_is64 = (w[1001] == 0 && w[1000] > 0) ? 1 : 0;
    }
}
__device__ __forceinline__ int load_mol(const void* batch, int i) {
    if (g_is64) return (int)((const long long*)batch)[i];
    return ((const int*)batch)[i];
}

// ---------------------------------------------------------------------------
// smem layout (byte offsets from 128-aligned base)
// ---------------------------------------------------------------------------
#define OFF_A    0
#define OFF_W    (OFF_A + A_BYTES)          // 67584
#define OFF_B1   (OFF_W + W_BYTES)          // 202752
#define OFF_B2   (OFF_B1 + 1024)
#define OFF_W3   (OFF_B2 + 1024)
#define OFF_MOL  (OFF_W3 + 1024)
#define OFF_ROW  (OFF_MOL + 4096)
#define OFF_MBAR (OFF_ROW + 512)
#define SMEM_BYTES (OFF_MBAR + 8 + 128)

// 32x64 GEMM per warp: acc[mi][ni][4], mi in {0,1} (16-row halves), ni in 0..7 (8-col tiles)
__device__ __forceinline__ void gemm_tile(float acc[2][8][4], uint32_t aA0, uint32_t aA1, uint32_t aW) {
#pragma unroll
    for (int k = 0; k < 16; k++) {
        uint32_t a0[4], a1[4];
        ldsm_x4(a0, aA0 + k * 32);
        ldsm_x4(a1, aA1 + k * 32);
#pragma unroll
        for (int g = 0; g < 4; g++) {
            uint32_t b[4];
            ldsm_x4_t(b, aW + k * 16 * LDA_B + g * 32);
            mma16816(acc[0][2 * g],     a0, b[0], b[1]);
            mma16816(acc[0][2 * g + 1], a0, b[2], b[3]);
            mma16816(acc[1][2 * g],     a1, b[0], b[1]);
            mma16816(acc[1][2 * g + 1], a1, b[2], b[3]);
        }
    }
}

__global__ void __launch_bounds__(NTHREADS, 1)
fused_mlp(const float* __restrict__ X, const void* __restrict__ batch,
          const float* __restrict__ b1, const float* __restrict__ b2,
          const float* __restrict__ W3, const float* __restrict__ b3,
          float* __restrict__ out, int n_atoms) {
    extern __shared__ char sraw[];
    uint32_t sb = smem_u32(sraw);
    uint32_t wb = (sb + 127) & ~127u;
    char* base = sraw + (wb - sb);

    char*  s_A    = base + OFF_A;
    float* b1s    = (float*)(base + OFF_B1);
    float* b2s    = (float*)(base + OFF_B2);
    float* w3s    = (float*)(base + OFF_W3);
    float* molacc = (float*)(base + OFF_MOL);
    float* rowsum = (float*)(base + OFF_ROW);
    const uint32_t mbar = wb + OFF_MBAR;
    const uint32_t A_u = wb + OFF_A, W_u = wb + OFF_W;

    const int tid = threadIdx.x;
    const int wid = tid >> 5, lane = tid & 31;
    const int wm = wid >> 2, wn = wid & 3;
    const int row0 = blockIdx.x * TM;

    if (tid == 0) {
        MBARRIER_INIT(mbar, 1);
        FENCE_PROXY_ASYNC();
        MBARRIER_EXPECT_TX(mbar, W_BYTES);
        bulk_g2s(W_u, g_W1img, W_BYTES, mbar);      // W1 -> smem (async)
    }
    for (int i = tid; i < NMOL; i += NTHREADS) molacc[i] = 0.0f;
    if (tid < TM) rowsum[tid] = 0.0f;
    if (tid < FEAT) { b1s[tid] = b1[tid]; b2s[tid] = b2[tid]; w3s[tid] = W3[tid]; }

    // ---- stage X tile: coalesced fp32 LDG -> bf16 smem (padded ld) ----
    for (int idx = tid * 4; idx < TM * FEAT; idx += NTHREADS * 4) {
        int r = idx >> 8, c = idx & 255;
        int grow = row0 + r;
        float4 v = make_float4(0.f, 0.f, 0.f, 0.f);
        if (grow < n_atoms) v = *(const float4*)(X + (size_t)grow * FEAT + c);
        __nv_bfloat162 h0 = __floats2bfloat162_rn(v.x, v.y);
        __nv_bfloat162 h1 = __floats2bfloat162_rn(v.z, v.w);
        uint2 wv; wv.x = *(uint32_t*)&h0; wv.y = *(uint32_t*)&h1;
        *(uint2*)(s_A + r * LDA_B + c * 2) = wv;
    }
    __syncthreads();
    MBARRIER_WAIT_PARITY(mbar, 0);

    // ldmatrix base addresses for this warp
    const uint32_t aA0 = A_u + (uint32_t)((wm * 32 + (lane & 15)) * LDA_B + (lane >> 4) * 16);
    const uint32_t aA1 = aA0 + 16 * LDA_B;
    const uint32_t aW  = W_u + (uint32_t)((lane & 15) * LDA_B + (wn * 64 + (lane >> 4) * 8) * 2);

    const int g = lane >> 2, q = lane & 3;

    // ================= layer 1 =================
    float acc[2][8][4];
#pragma unroll
    for (int mi = 0; mi < 2; mi++)
#pragma unroll
        for (int ni = 0; ni < 8; ni++)
#pragma unroll
            for (int j = 0; j < 4; j++) acc[mi][ni][j] = 0.0f;

    gemm_tile(acc, aA0, aA1, aW);
    __syncthreads();                         // all reads of A and W done

    if (tid == 0) {                          // start W2 copy, overlap with epilogue
        MBARRIER_EXPECT_TX(mbar, W_BYTES);
        bulk_g2s(W_u, g_W2img, W_BYTES, mbar);
    }

    // epilogue 1: bias + silu in registers -> bf16 back into A
#pragma unroll
    for (int mi = 0; mi < 2; mi++) {
        int r0 = wm * 32 + mi * 16 + g;
#pragma unroll
        for (int ni = 0; ni < 8; ni++) {
            int col = wn * 64 + ni * 8 + 2 * q;
            float bb0 = b1s[col], bb1 = b1s[col + 1];
            __nv_bfloat162 h0 = __floats2bfloat162_rn(silu(acc[mi][ni][0] + bb0),
                                                      silu(acc[mi][ni][1] + bb1));
            __nv_bfloat162 h1 = __floats2bfloat162_rn(silu(acc[mi][ni][2] + bb0),
                                                      silu(acc[mi][ni][3] + bb1));
            *(uint32_t*)(s_A + r0 * LDA_B + col * 2)       = *(uint32_t*)&h0;
            *(uint32_t*)(s_A + (r0 + 8) * LDA_B + col * 2) = *(uint32_t*)&h1;
#pragma unroll
            for (int j = 0; j < 4; j++) acc[mi][ni][j] = 0.0f;
        }
    }
    __syncthreads();
    MBARRIER_WAIT_PARITY(mbar, 1);

    // ================= layer 2 =================
    gemm_tile(acc, aA0, aA1, aW);

    // epilogue 2: bias + silu + dot(W3) folded in registers
#pragma unroll
    for (int mi = 0; mi < 2; mi++) {
        float p0 = 0.0f, p1 = 0.0f;
#pragma unroll
        for (int ni = 0; ni < 8; ni++) {
            int col = wn * 64 + ni * 8 + 2 * q;
            float bb0 = b2s[col], bb1 = b2s[col + 1];
            float w0 = w3s[col], w1 = w3s[col + 1];
            p0 += silu(acc[mi][ni][0] + bb0) * w0 + silu(acc[mi][ni][1] + bb1) * w1;
            p1 += silu(acc[mi][ni][2] + bb0) * w0 + silu(acc[mi][ni][3] + bb1) * w1;
        }
        // reduce over the 4 lanes sharing a row (q = 0..3)
        p0 += __shfl_xor_sync(0xffffffffu, p0, 1); p0 += __shfl_xor_sync(0xffffffffu, p0, 2);
        p1 += __shfl_xor_sync(0xffffffffu, p1, 1); p1 += __shfl_xor_sync(0xffffffffu, p1, 2);
        if (q == 0) {
            int r0 = wm * 32 + mi * 16 + g;
            atomicAdd(&rowsum[r0], p0);
            atomicAdd(&rowsum[r0 + 8], p1);
        }
    }
    __syncthreads();

    // ---- pooling ----
    const float b3v = *b3;
    if (tid < TM) {
        int grow = row0 + tid;
        if (grow < n_atoms) {
            int mol = load_mol(batch, grow);
            atomicAdd(&molacc[mol], rowsum[tid] + b3v);
        }
    }
    __syncthreads();
    for (int i = tid; i < NMOL; i += NTHREADS) {
        float v = molacc[i];
        if (v != 0.0f) atomicAdd(out + i, v * kScale);
    }
}

// ---------------------------------------------------------------------------
extern "C" void kernel_launch(void* const* d_in, const int* in_sizes, int n_in,
                              void* d_out, int out_size) {
    const float* atom_node = (const float*)d_in[0];
    const void*  batch     = d_in[1];
    const float* W1 = (const float*)d_in[2];
    const float* b1 = (const float*)d_in[3];
    const float* W2 = (const float*)d_in[4];
    const float* b2 = (const float*)d_in[5];
    const float* W3 = (const float*)d_in[6];
    const float* b3 = (const float*)d_in[7];
    float* out = (float*)d_out;
    const int n_atoms = in_sizes[1];

    convert_weights<<<(FEAT * FEAT + 255) / 256, 256>>>(W1, W2);
    init_out<<<(NMOL + 255) / 256, 256>>>(batch, out);

    cudaFuncSetAttribute(fused_mlp, cudaFuncAttributeMaxDynamicSharedMemorySize, SMEM_BYTES);
    int blocks = (n_atoms + TM - 1) / TM;
    fused_mlp<<<blocks, NTHREADS, SMEM_BYTES>>>(atom_node, batch, b1, b2, W3, b3, out, n_atoms);
}

// round 4
// speedup vs baseline: 3.0379x; 1.1308x over previous
#include <cuda_runtime.h>
#include <cuda_bf16.h>
#include <math.h>
#include <stdint.h>

#define FEAT     256
#define NMOL     1024
#define TM       64
#define NTHREADS 512            // 16 warps: 2 (M) x 8 (N)
#define NCTA     152
#define LDA      264            // padded W row stride (bf16 elems)
#define LDA_B    (LDA * 2)
#define W_BYTES  (FEAT * LDA * 2)   // 135168
#define A_BYTES  (TM * 512)         // 32768 (bf16, 512B rows, xor-swizzled)

__device__ __constant__ float kScale = 5.992277830325989f;
__device__ __constant__ float kShift = -406274.63784969115f;

__device__ __align__(128) __nv_bfloat16 g_W1img[FEAT * LDA];
__device__ __align__(128) __nv_bfloat16 g_W2img[FEAT * LDA];
__device__ int g_is64;

// ---------------------------------------------------------------------------
__device__ __forceinline__ uint32_t smem_u32(const void* p) {
    uint32_t a;
    asm("{ .reg .u64 t; cvta.to.shared.u64 t, %1; cvt.u32.u64 %0, t; }" : "=r"(a) : "l"(p));
    return a;
}
#define MBARRIER_INIT(addr, cnt) \
    asm volatile("mbarrier.init.shared.b64 [%0], %1;" :: "r"(addr), "r"(cnt) : "memory")
#define MBARRIER_EXPECT_TX(addr, bytes) \
    asm volatile("mbarrier.arrive.expect_tx.shared.b64 _, [%0], %1;" :: "r"(addr), "r"(bytes) : "memory")
#define MBARRIER_WAIT_PARITY(addr, ph) do { \
    uint32_t _m = (addr); uint32_t _p = (ph); uint32_t _d; \
    asm volatile("{ .reg .pred p; mbarrier.try_wait.parity.acquire.cta.shared::cta.b64 p, [%1], %2; selp.b32 %0,1,0,p; }" \
        : "=r"(_d) : "r"(_m), "r"(_p) : "memory"); \
    if (!_d) { asm volatile("{ .reg .pred P1; WL_%=: mbarrier.try_wait.parity.acquire.cta.shared::cta.b64 P1, [%0], %1, 0x989680; @P1 bra.uni WD_%=; bra.uni WL_%=; WD_%=: }" \
        :: "r"(_m), "r"(_p) : "memory"); } \
} while (0)
#define FENCE_PROXY_ASYNC() asm volatile("fence.proxy.async.shared::cta;" ::: "memory")

__device__ __forceinline__ void bulk_g2s(uint32_t dst, const void* src, uint32_t bytes, uint32_t mbar) {
    asm volatile("cp.async.bulk.shared::cta.global.mbarrier::complete_tx::bytes [%0], [%1], %2, [%3];"
                 :: "r"(dst), "l"(src), "r"(bytes), "r"(mbar) : "memory");
}
__device__ __forceinline__ void ldsm_x4(uint32_t* r, uint32_t addr) {
    asm volatile("ldmatrix.sync.aligned.m8n8.x4.shared.b16 {%0,%1,%2,%3}, [%4];"
                 : "=r"(r[0]), "=r"(r[1]), "=r"(r[2]), "=r"(r[3]) : "r"(addr));
}
__device__ __forceinline__ void ldsm_x4_t(uint32_t* r, uint32_t addr) {
    asm volatile("ldmatrix.sync.aligned.m8n8.x4.trans.shared.b16 {%0,%1,%2,%3}, [%4];"
                 : "=r"(r[0]), "=r"(r[1]), "=r"(r[2]), "=r"(r[3]) : "r"(addr));
}
__device__ __forceinline__ void mma16816(float* c, const uint32_t* a, uint32_t b0, uint32_t b1) {
    asm volatile("mma.sync.aligned.m16n8k16.row.col.f32.bf16.bf16.f32 "
                 "{%0,%1,%2,%3}, {%4,%5,%6,%7}, {%8,%9}, {%0,%1,%2,%3};"
                 : "+f"(c[0]), "+f"(c[1]), "+f"(c[2]), "+f"(c[3])
                 : "r"(a[0]), "r"(a[1]), "r"(a[2]), "r"(a[3]), "r"(b0), "r"(b1));
}
__device__ __forceinline__ float silu(float v) { return v * (1.0f / (1.0f + __expf(-v))); }

// ---------------------------------------------------------------------------
// Prep: W -> padded bf16 images, out init, batch dtype probe  (ONE kernel so
// ncu -s 5 lands on fused_mlp)
// ---------------------------------------------------------------------------
__global__ void prep(const float* __restrict__ W1, const float* __restrict__ W2,
                     const void* __restrict__ batch, float* __restrict__ out) {
    int i = blockIdx.x * blockDim.x + threadIdx.x;
    if (i < FEAT * FEAT) {
        int k = i >> 8, n = i & 255;
        g_W1img[k * LDA + n] = __float2bfloat16(W1[i]);
        g_W2img[k * LDA + n] = __float2bfloat16(W2[i]);
    }
    if (i < NMOL) out[i] = kShift;
    if (i == 0) {
        const int* w = (const int*)batch;
        g_is64 = (w[1001] == 0 && w[1000] > 0) ? 1 : 0;
    }
}
__device__ __forceinline__ int load_mol(const void* batch, int i) {
    if (g_is64) return (int)((const long long*)batch)[i];
    return ((const int*)batch)[i];
}

// ---------------------------------------------------------------------------
// smem layout
// ---------------------------------------------------------------------------
#define OFF_A    0
#define OFF_W    (OFF_A + A_BYTES)           // 32768
#define OFF_B1   (OFF_W + W_BYTES)           // 167936
#define OFF_B2   (OFF_B1 + 1024)
#define OFF_W3   (OFF_B2 + 1024)
#define OFF_MOL  (OFF_W3 + 1024)             // 4096
#define OFF_ROW  (OFF_MOL + 4096)            // 256
#define OFF_MBAR (OFF_ROW + 256)
#define SMEM_BYTES (OFF_MBAR + 8 + 128)

// X prefetch: 8 float4 per thread -> 8 uint2 (bf16x2 pairs)
__device__ __forceinline__ void prefetch_x(uint2 px[8], const float* __restrict__ X,
                                           int row0, int n_atoms, int tid) {
#pragma unroll
    for (int i = 0; i < 8; i++) {
        int idx = tid * 4 + i * 2048;
        int r = idx >> 8, c = idx & 255;
        int grow = row0 + r;
        float4 v = make_float4(0.f, 0.f, 0.f, 0.f);
        if (grow < n_atoms) v = *(const float4*)(X + (size_t)grow * FEAT + c);
        __nv_bfloat162 h0 = __floats2bfloat162_rn(v.x, v.y);
        __nv_bfloat162 h1 = __floats2bfloat162_rn(v.z, v.w);
        px[i].x = *(uint32_t*)&h0; px[i].y = *(uint32_t*)&h1;
    }
}
__device__ __forceinline__ void store_x(const uint2 px[8], char* s_A, int tid) {
#pragma unroll
    for (int i = 0; i < 8; i++) {
        int idx = tid * 4 + i * 2048;
        int r = idx >> 8, c = idx & 255;
        uint32_t off = (uint32_t)(r * 512 + ((c * 2) ^ ((r & 7) << 4)));
        *(uint2*)(s_A + off) = px[i];
    }
}

// 32x32 per-warp GEMM: acc[mi(16rows)][ni(8cols)][4]
__device__ __forceinline__ void gemm_tile(float acc[2][4][4], uint32_t A_u, uint32_t W_u,
                                          int wm, int wn, int lane) {
    const int r0 = wm * 32 + (lane & 15);
    const uint32_t x0 = (uint32_t)((r0 & 7) << 4);     // (r0+16)&7 == r0&7
    const uint32_t aA0 = A_u + r0 * 512;
    const uint32_t aA1 = aA0 + 16 * 512;
    const int s16 = (lane >> 4) * 16;
    const uint32_t aW = W_u + (uint32_t)((lane & 15) * LDA_B + (wn * 32 + (lane >> 4) * 8) * 2);
#pragma unroll
    for (int k = 0; k < 16; k++) {
        uint32_t cb = (uint32_t)(k * 32 + s16) ^ x0;
        uint32_t a0[4], a1[4], b0[4], b1[4];
        ldsm_x4(a0, aA0 + cb);
        ldsm_x4(a1, aA1 + cb);
        ldsm_x4_t(b0, aW + k * 16 * LDA_B);
        ldsm_x4_t(b1, aW + k * 16 * LDA_B + 32);
        mma16816(acc[0][0], a0, b0[0], b0[1]);
        mma16816(acc[0][1], a0, b0[2], b0[3]);
        mma16816(acc[0][2], a0, b1[0], b1[1]);
        mma16816(acc[0][3], a0, b1[2], b1[3]);
        mma16816(acc[1][0], a1, b0[0], b0[1]);
        mma16816(acc[1][1], a1, b0[2], b0[3]);
        mma16816(acc[1][2], a1, b1[0], b1[1]);
        mma16816(acc[1][3], a1, b1[2], b1[3]);
    }
}

__global__ void __launch_bounds__(NTHREADS, 1)
fused_mlp(const float* __restrict__ X, const void* __restrict__ batch,
          const float* __restrict__ b1, const float* __restrict__ b2,
          const float* __restrict__ W3, const float* __restrict__ b3,
          float* __restrict__ out, int n_atoms) {
    extern __shared__ char sraw[];
    uint32_t sb = smem_u32(sraw);
    uint32_t wb = (sb + 127) & ~127u;
    char* base = sraw + (wb - sb);

    char*  s_A    = base + OFF_A;
    float* b1s    = (float*)(base + OFF_B1);
    float* b2s    = (float*)(base + OFF_B2);
    float* w3s    = (float*)(base + OFF_W3);
    float* molacc = (float*)(base + OFF_MOL);
    float* rowsum = (float*)(base + OFF_ROW);
    const uint32_t mbar = wb + OFF_MBAR;
    const uint32_t A_u = wb + OFF_A, W_u = wb + OFF_W;

    const int tid = threadIdx.x;
    const int wid = tid >> 5, lane = tid & 31;
    const int wm = wid >> 3, wn = wid & 7;
    const int g = lane >> 2, q = lane & 3;
    const int stride = gridDim.x * TM;

    if (tid == 0) {
        MBARRIER_INIT(mbar, 1);
        FENCE_PROXY_ASYNC();
        MBARRIER_EXPECT_TX(mbar, W_BYTES);
        bulk_g2s(W_u, g_W1img, W_BYTES, mbar);
    }
    for (int i = tid; i < NMOL; i += NTHREADS) molacc[i] = 0.0f;
    if (tid < FEAT) { b1s[tid] = b1[tid]; b2s[tid] = b2[tid]; w3s[tid] = W3[tid]; }
    const float b3v = *b3;

    int row0 = blockIdx.x * TM;
    uint2 px[8];
    prefetch_x(px, X, row0, n_atoms, tid);
    int wph = 0;
    __syncthreads();

    while (row0 < n_atoms) {
        // ---- materialize X tile, zero rowsum ----
        store_x(px, s_A, tid);
        if (tid < TM) rowsum[tid] = 0.0f;
        __syncthreads();

        MBARRIER_WAIT_PARITY(mbar, wph & 1);          // W1 in smem

        // ---- layer 1 ----
        float acc[2][4][4];
#pragma unroll
        for (int mi = 0; mi < 2; mi++)
#pragma unroll
            for (int ni = 0; ni < 4; ni++)
#pragma unroll
                for (int j = 0; j < 4; j++) acc[mi][ni][j] = 0.0f;
        gemm_tile(acc, A_u, W_u, wm, wn, lane);
        __syncthreads();                              // A + W reads done

        if (tid == 0) { MBARRIER_EXPECT_TX(mbar, W_BYTES); bulk_g2s(W_u, g_W2img, W_BYTES, mbar); }
        wph++;

        const int next_row0 = row0 + stride;
        prefetch_x(px, X, next_row0, n_atoms, tid);   // LDGs overlap epi1 + gemm2

        // ---- epilogue 1: bias+silu -> bf16 back into A ----
#pragma unroll
        for (int mi = 0; mi < 2; mi++) {
            int r0 = wm * 32 + mi * 16 + g;
            uint32_t rb = (uint32_t)(r0 * 512), xr = (uint32_t)((r0 & 7) << 4);
#pragma unroll
            for (int ni = 0; ni < 4; ni++) {
                int col = wn * 32 + ni * 8 + 2 * q;
                float bb0 = b1s[col], bb1 = b1s[col + 1];
                __nv_bfloat162 h0 = __floats2bfloat162_rn(silu(acc[mi][ni][0] + bb0),
                                                          silu(acc[mi][ni][1] + bb1));
                __nv_bfloat162 h1 = __floats2bfloat162_rn(silu(acc[mi][ni][2] + bb0),
                                                          silu(acc[mi][ni][3] + bb1));
                *(uint32_t*)(s_A + rb + ((col * 2) ^ xr)) = *(uint32_t*)&h0;
                *(uint32_t*)(s_A + rb + 8 * 512 + ((col * 2) ^ xr)) = *(uint32_t*)&h1;
#pragma unroll
                for (int j = 0; j < 4; j++) acc[mi][ni][j] = 0.0f;
            }
        }
        __syncthreads();
        MBARRIER_WAIT_PARITY(mbar, wph & 1);          // W2 in smem

        // ---- layer 2 ----
        gemm_tile(acc, A_u, W_u, wm, wn, lane);

        // ---- epilogue 2: bias+silu+dot(W3), register-only ----
#pragma unroll
        for (int mi = 0; mi < 2; mi++) {
            float p0 = 0.0f, p1 = 0.0f;
#pragma unroll
            for (int ni = 0; ni < 4; ni++) {
                int col = wn * 32 + ni * 8 + 2 * q;
                float bb0 = b2s[col], bb1 = b2s[col + 1];
                float w0 = w3s[col], w1 = w3s[col + 1];
                p0 += silu(acc[mi][ni][0] + bb0) * w0 + silu(acc[mi][ni][1] + bb1) * w1;
                p1 += silu(acc[mi][ni][2] + bb0) * w0 + silu(acc[mi][ni][3] + bb1) * w1;
            }
            p0 += __shfl_xor_sync(0xffffffffu, p0, 1); p0 += __shfl_xor_sync(0xffffffffu, p0, 2);
            p1 += __shfl_xor_sync(0xffffffffu, p1, 1); p1 += __shfl_xor_sync(0xffffffffu, p1, 2);
            if (q == 0) {
                int r0 = wm * 32 + mi * 16 + g;
                atomicAdd(&rowsum[r0], p0);
                atomicAdd(&rowsum[r0 + 8], p1);
            }
        }
        __syncthreads();                              // rowsum ready; W reads done

        const bool has_next = next_row0 < n_atoms;
        if (tid == 0 && has_next) { MBARRIER_EXPECT_TX(mbar, W_BYTES); bulk_g2s(W_u, g_W1img, W_BYTES, mbar); }
        wph++;

        // ---- pooling into persistent smem molacc ----
        if (tid < TM) {
            int grow = row0 + tid;
            if (grow < n_atoms) {
                int mol = load_mol(batch, grow);
                atomicAdd(&molacc[mol], rowsum[tid] + b3v);
            }
        }
        __syncthreads();
        row0 = next_row0;
    }

    // ---- single global flush per CTA ----
    for (int i = tid; i < NMOL; i += NTHREADS) {
        float v = molacc[i];
        if (v != 0.0f) atomicAdd(out + i, v * kScale);
    }
}

// ---------------------------------------------------------------------------
extern "C" void kernel_launch(void* const* d_in, const int* in_sizes, int n_in,
                              void* d_out, int out_size) {
    const float* atom_node = (const float*)d_in[0];
    const void*  batch     = d_in[1];
    const float* W1 = (const float*)d_in[2];
    const float* b1 = (const float*)d_in[3];
    const float* W2 = (const float*)d_in[4];
    const float* b2 = (const float*)d_in[5];
    const float* W3 = (const float*)d_in[6];
    const float* b3 = (const float*)d_in[7];
    float* out = (float*)d_out;
    const int n_atoms = in_sizes[1];

    prep<<<(FEAT * FEAT + 255) / 256, 256>>>(W1, W2, batch, out);

    cudaFuncSetAttribute(fused_mlp, cudaFuncAttributeMaxDynamicSharedMemorySize, SMEM_BYTES);
    int ntiles = (n_atoms + TM - 1) / TM;
    int grid = ntiles < NCTA ? ntiles : NCTA;
    fused_mlp<<<grid, NTHREADS, SMEM_BYTES>>>(atom_node, batch, b1, b2, W3, b3, out, n_atoms);
}

// round 5
// speedup vs baseline: 3.8188x; 1.2571x over previous
#include <cuda_runtime.h>
#include <cuda_bf16.h>
#include <math.h>
#include <stdint.h>

#define FEAT     256
#define NMOL     1024
#define TM       64
#define NTHREADS 512            // 16 warps: 2 (M) x 8 (N)
#define NCTA     152
#define WIMG_B   65536          // one fp8 weight image (256 n-rows x 256 k-bytes)
#define A_BYTES  (TM * 256)     // 16384 fp8 A tile

__device__ __constant__ float kScale = 5.992277830325989f;
__device__ __constant__ float kShift = -406274.63784969115f;

// fp8 e4m3 weight images, n-major, 16B-granule XOR swizzle per row
__device__ __align__(128) unsigned char g_Wimg[2][WIMG_B];
__device__ int g_is64;

// ---------------------------------------------------------------------------
__device__ __forceinline__ uint32_t smem_u32(const void* p) {
    uint32_t a;
    asm("{ .reg .u64 t; cvta.to.shared.u64 t, %1; cvt.u32.u64 %0, t; }" : "=r"(a) : "l"(p));
    return a;
}
#define MBARRIER_INIT(addr, cnt) \
    asm volatile("mbarrier.init.shared.b64 [%0], %1;" :: "r"(addr), "r"(cnt) : "memory")
#define MBARRIER_EXPECT_TX(addr, bytes) \
    asm volatile("mbarrier.arrive.expect_tx.shared.b64 _, [%0], %1;" :: "r"(addr), "r"(bytes) : "memory")
#define MBARRIER_WAIT_PARITY(addr, ph) do { \
    uint32_t _m = (addr); uint32_t _p = (ph); uint32_t _d; \
    asm volatile("{ .reg .pred p; mbarrier.try_wait.parity.acquire.cta.shared::cta.b64 p, [%1], %2; selp.b32 %0,1,0,p; }" \
        : "=r"(_d) : "r"(_m), "r"(_p) : "memory"); \
    if (!_d) { asm volatile("{ .reg .pred P1; WL_%=: mbarrier.try_wait.parity.acquire.cta.shared::cta.b64 P1, [%0], %1, 0x989680; @P1 bra.uni WD_%=; bra.uni WL_%=; WD_%=: }" \
        :: "r"(_m), "r"(_p) : "memory"); } \
} while (0)
#define FENCE_PROXY_ASYNC() asm volatile("fence.proxy.async.shared::cta;" ::: "memory")

__device__ __forceinline__ void bulk_g2s(uint32_t dst, const void* src, uint32_t bytes, uint32_t mbar) {
    asm volatile("cp.async.bulk.shared::cta.global.mbarrier::complete_tx::bytes [%0], [%1], %2, [%3];"
                 :: "r"(dst), "l"(src), "r"(bytes), "r"(mbar) : "memory");
}
__device__ __forceinline__ void ldsm_x4(uint32_t* r, uint32_t addr) {
    asm volatile("ldmatrix.sync.aligned.m8n8.x4.shared.b16 {%0,%1,%2,%3}, [%4];"
                 : "=r"(r[0]), "=r"(r[1]), "=r"(r[2]), "=r"(r[3]) : "r"(addr));
}
// fp8 e4m3 MMA, fp32 accum
__device__ __forceinline__ void mma_fp8(float* c, const uint32_t* a, uint32_t b0, uint32_t b1) {
    asm volatile("mma.sync.aligned.m16n8k32.row.col.f32.e4m3.e4m3.f32 "
                 "{%0,%1,%2,%3}, {%4,%5,%6,%7}, {%8,%9}, {%0,%1,%2,%3};"
                 : "+f"(c[0]), "+f"(c[1]), "+f"(c[2]), "+f"(c[3])
                 : "r"(a[0]), "r"(a[1]), "r"(a[2]), "r"(a[3]), "r"(b0), "r"(b1));
}
// pack2: low byte = lo, high byte = hi (first PTX src -> upper byte)
__device__ __forceinline__ unsigned short f2e4m3x2(float lo, float hi) {
    unsigned short t;
    asm("cvt.rn.satfinite.e4m3x2.f32 %0, %1, %2;" : "=h"(t) : "f"(hi), "f"(lo));
    return t;
}
__device__ __forceinline__ float fast_silu(float x) {
    float t;
    asm("tanh.approx.f32 %0, %1;" : "=f"(t) : "f"(0.5f * x));
    return x * (0.5f * t + 0.5f);
}
// swizzled byte offset within a 256B row: granule g, row r
__device__ __forceinline__ uint32_t swz(int r, int cbyte) {
    return (uint32_t)(r * 256 + ((((cbyte >> 4) ^ (r & 7)) << 4) | (cbyte & 15)));
}

// ---------------------------------------------------------------------------
// Prep: W -> fp8 swizzled n-major images + out init + batch dtype probe
// ---------------------------------------------------------------------------
__global__ void prep(const float* __restrict__ W1, const float* __restrict__ W2,
                     const void* __restrict__ batch, float* __restrict__ out) {
    __shared__ float s[32][33];
    int tile = blockIdx.x;                   // 64 tiles of 32(k) x 32(n)
    int k0 = (tile >> 3) * 32, n0 = (tile & 7) * 32;
    const float* W = blockIdx.y ? W2 : W1;
    unsigned char* img = g_Wimg[blockIdx.y];
    int t = threadIdx.x;
    {   // coalesced read of W[k][n]
        int kk = t >> 3, nn = (t & 7) * 4;
        float4 v = *(const float4*)&W[(k0 + kk) * FEAT + n0 + nn];
        s[kk][nn] = v.x; s[kk][nn + 1] = v.y; s[kk][nn + 2] = v.z; s[kk][nn + 3] = v.w;
    }
    __syncthreads();
    {   // write 4 consecutive k-bytes for one n
        int nn = t >> 3, kk = (t & 7) * 4;
        int n = n0 + nn, k = k0 + kk;
        unsigned short p0 = f2e4m3x2(s[kk][nn],     s[kk + 1][nn]);
        unsigned short p1 = f2e4m3x2(s[kk + 2][nn], s[kk + 3][nn]);
        uint32_t val = (uint32_t)p0 | ((uint32_t)p1 << 16);
        *(uint32_t*)(img + swz(n, k)) = val;
    }
    if (blockIdx.y == 0 && blockIdx.x < 4) {
        int gi = blockIdx.x * 256 + t;
        out[gi] = kShift;
        if (gi == 0) {
            const int* w = (const int*)batch;
            g_is64 = (w[1001] == 0 && w[1000] > 0) ? 1 : 0;
        }
    }
}
__device__ __forceinline__ int load_mol(const void* batch, int i) {
    if (g_is64) return (int)((const long long*)batch)[i];
    return ((const int*)batch)[i];
}

// ---------------------------------------------------------------------------
// smem layout
// ---------------------------------------------------------------------------
#define OFF_A    0
#define OFF_W    (OFF_A + A_BYTES)           // 16384
#define OFF_B1   (OFF_W + 2 * WIMG_B)        // 147456
#define OFF_B2   (OFF_B1 + 1024)
#define OFF_W3   (OFF_B2 + 1024)
#define OFF_MOL  (OFF_W3 + 1024)             // 4096
#define OFF_ROW  (OFF_MOL + 4096)            // 256
#define OFF_MBAR (OFF_ROW + 256)
#define SMEM_BYTES (OFF_MBAR + 8 + 128)

// X prefetch: per thread 8 x float4 -> 8 x uint32 (4 e4m3 each)
__device__ __forceinline__ void prefetch_x(uint32_t px[8], const float* __restrict__ X,
                                           int row0, int n_atoms, int tid) {
#pragma unroll
    for (int i = 0; i < 8; i++) {
        int idx = tid * 4 + i * 2048;
        int r = idx >> 8, c = idx & 255;
        int grow = row0 + r;
        float4 v = make_float4(0.f, 0.f, 0.f, 0.f);
        if (grow < n_atoms) v = *(const float4*)(X + (size_t)grow * FEAT + c);
        unsigned short p0 = f2e4m3x2(v.x, v.y);
        unsigned short p1 = f2e4m3x2(v.z, v.w);
        px[i] = (uint32_t)p0 | ((uint32_t)p1 << 16);
    }
}
__device__ __forceinline__ void store_x(const uint32_t px[8], char* s_A, int tid) {
#pragma unroll
    for (int i = 0; i < 8; i++) {
        int idx = tid * 4 + i * 2048;
        int r = idx >> 8, c = idx & 255;
        *(uint32_t*)(s_A + swz(r, c)) = px[i];
    }
}

// 32x32 per-warp FP8 GEMM: acc[mi(16 rows)][ni(8 cols)][4]
__device__ __forceinline__ void gemm_fp8(float acc[2][4][4], uint32_t A_u, uint32_t W_u,
                                         int wm, int wn, int lane) {
    // A lane addressing: matrix m=lane>>3 -> row=(m&1)*8+(lane&7), k-half=m>>1
    const int rowA = wm * 32 + (lane & 7) + ((lane >> 3) & 1) * 8;
    const int gA   = lane >> 4;           // k-half select
    const int rxA  = rowA & 7;
    const uint32_t baseA = A_u + rowA * 256;
    // B lane addressing: matrix m -> n-group=m>>1, k-half=m&1
    const int rowB = wn * 32 + (lane >> 4) * 8 + (lane & 7);
    const int gB   = (lane >> 3) & 1;
    const int rxB  = rowB & 7;
    const uint32_t baseB = W_u + rowB * 256;
#pragma unroll
    for (int s = 0; s < 8; s++) {
        uint32_t a0[4], a1[4], b0[4], b1[4];
        uint32_t oA = (uint32_t)(((2 * s + gA) ^ rxA) << 4);
        uint32_t oB = (uint32_t)(((2 * s + gB) ^ rxB) << 4);
        ldsm_x4(a0, baseA + oA);                   // rows wm*32..+15
        ldsm_x4(a1, baseA + 16 * 256 + oA);        // rows +16..+31
        ldsm_x4(b0, baseB + oB);                   // n-groups 0,1
        ldsm_x4(b1, baseB + 16 * 256 + oB);        // n-groups 2,3
        mma_fp8(acc[0][0], a0, b0[0], b0[1]);
        mma_fp8(acc[1][0], a1, b0[0], b0[1]);
        mma_fp8(acc[0][1], a0, b0[2], b0[3]);
        mma_fp8(acc[1][1], a1, b0[2], b0[3]);
        mma_fp8(acc[0][2], a0, b1[0], b1[1]);
        mma_fp8(acc[1][2], a1, b1[0], b1[1]);
        mma_fp8(acc[0][3], a0, b1[2], b1[3]);
        mma_fp8(acc[1][3], a1, b1[2], b1[3]);
    }
}

__global__ void __launch_bounds__(NTHREADS, 1)
fused_mlp(const float* __restrict__ X, const void* __restrict__ batch,
          const float* __restrict__ b1, const float* __restrict__ b2,
          const float* __restrict__ W3, const float* __restrict__ b3,
          float* __restrict__ out, int n_atoms) {
    extern __shared__ char sraw[];
    uint32_t sb = smem_u32(sraw);
    uint32_t wb = (sb + 127) & ~127u;
    char* base = sraw + (wb - sb);

    char*  s_A    = base + OFF_A;
    float* b1s    = (float*)(base + OFF_B1);
    float* b2s    = (float*)(base + OFF_B2);
    float* w3s    = (float*)(base + OFF_W3);
    float* molacc = (float*)(base + OFF_MOL);
    float* rowsum = (float*)(base + OFF_ROW);
    const uint32_t mbar = wb + OFF_MBAR;
    const uint32_t A_u = wb + OFF_A, W_u = wb + OFF_W;

    const int tid = threadIdx.x;
    const int wid = tid >> 5, lane = tid & 31;
    const int wm = wid >> 3, wn = wid & 7;
    const int g = lane >> 2, q = lane & 3;
    const int stride = gridDim.x * TM;

    if (tid == 0) {
        MBARRIER_INIT(mbar, 1);
        FENCE_PROXY_ASYNC();
        MBARRIER_EXPECT_TX(mbar, 2 * WIMG_B);
        bulk_g2s(W_u, &g_Wimg[0][0], 2 * WIMG_B, mbar);   // both W images, once
    }
    for (int i = tid; i < NMOL; i += NTHREADS) molacc[i] = 0.0f;
    if (tid < TM) rowsum[tid] = 0.0f;
    if (tid < FEAT) { b1s[tid] = b1[tid]; b2s[tid] = b2[tid]; w3s[tid] = W3[tid]; }
    const float b3v = *b3;

    int row0 = blockIdx.x * TM;
    uint32_t px[8];
    prefetch_x(px, X, row0, n_atoms, tid);
    __syncthreads();                       // mbarrier init visible
    MBARRIER_WAIT_PARITY(mbar, 0);         // weights resident (forever)

    while (row0 < n_atoms) {
        store_x(px, s_A, tid);
        __syncthreads();                   // A ready (+ first-iter biases)

        // ---- layer 1 ----
        float acc[2][4][4];
#pragma unroll
        for (int mi = 0; mi < 2; mi++)
#pragma unroll
            for (int ni = 0; ni < 4; ni++)
#pragma unroll
                for (int j = 0; j < 4; j++) acc[mi][ni][j] = 0.0f;
        gemm_fp8(acc, A_u, W_u, wm, wn, lane);
        __syncthreads();                   // A consumed

        const int next_row0 = row0 + stride;
        prefetch_x(px, X, next_row0, n_atoms, tid);   // overlaps epi1+gemm2

        // ---- epilogue 1: bias + silu -> fp8 back into A ----
#pragma unroll
        for (int mi = 0; mi < 2; mi++) {
            int r0 = wm * 32 + mi * 16 + g;
#pragma unroll
            for (int ni = 0; ni < 4; ni++) {
                int c0 = wn * 32 + ni * 8 + 2 * q;
                float bb0 = b1s[c0], bb1 = b1s[c0 + 1];
                unsigned short h0 = f2e4m3x2(fast_silu(acc[mi][ni][0] + bb0),
                                             fast_silu(acc[mi][ni][1] + bb1));
                unsigned short h1 = f2e4m3x2(fast_silu(acc[mi][ni][2] + bb0),
                                             fast_silu(acc[mi][ni][3] + bb1));
                *(unsigned short*)(s_A + swz(r0, c0))     = h0;
                *(unsigned short*)(s_A + swz(r0 + 8, c0)) = h1;
#pragma unroll
                for (int j = 0; j < 4; j++) acc[mi][ni][j] = 0.0f;
            }
        }
        __syncthreads();                   // A2 ready

        // ---- layer 2 ----
        gemm_fp8(acc, A_u, W_u + WIMG_B, wm, wn, lane);

        // ---- epilogue 2: bias + silu + dot(W3) ----
#pragma unroll
        for (int mi = 0; mi < 2; mi++) {
            float p0 = 0.0f, p1 = 0.0f;
#pragma unroll
            for (int ni = 0; ni < 4; ni++) {
                int c0 = wn * 32 + ni * 8 + 2 * q;
                float bb0 = b2s[c0], bb1 = b2s[c0 + 1];
                float w0 = w3s[c0], w1 = w3s[c0 + 1];
                p0 += fast_silu(acc[mi][ni][0] + bb0) * w0 + fast_silu(acc[mi][ni][1] + bb1) * w1;
                p1 += fast_silu(acc[mi][ni][2] + bb0) * w0 + fast_silu(acc[mi][ni][3] + bb1) * w1;
            }
            p0 += __shfl_xor_sync(0xffffffffu, p0, 1); p0 += __shfl_xor_sync(0xffffffffu, p0, 2);
            p1 += __shfl_xor_sync(0xffffffffu, p1, 1); p1 += __shfl_xor_sync(0xffffffffu, p1, 2);
            if (q == 0) {
                int r0 = wm * 32 + mi * 16 + g;
                atomicAdd(&rowsum[r0], p0);
                atomicAdd(&rowsum[r0 + 8], p1);
            }
        }
        __syncthreads();                   // rowsum ready, A consumed

        // ---- pooling (store_x of next iter is independent of rowsum/molacc) ----
        if (tid < TM) {
            int grow = row0 + tid;
            if (grow < n_atoms) {
                int mol = load_mol(batch, grow);
                atomicAdd(&molacc[mol], rowsum[tid] + b3v);
            }
            rowsum[tid] = 0.0f;
        }
        row0 = next_row0;
    }

    __syncthreads();
    for (int i = tid; i < NMOL; i += NTHREADS) {
        float v = molacc[i];
        if (v != 0.0f) atomicAdd(out + i, v * kScale);
    }
}

// ---------------------------------------------------------------------------
extern "C" void kernel_launch(void* const* d_in, const int* in_sizes, int n_in,
                              void* d_out, int out_size) {
    const float* atom_node = (const float*)d_in[0];
    const void*  batch     = d_in[1];
    const float* W1 = (const float*)d_in[2];
    const float* b1 = (const float*)d_in[3];
    const float* W2 = (const float*)d_in[4];
    const float* b2 = (const float*)d_in[5];
    const float* W3 = (const float*)d_in[6];
    const float* b3 = (const float*)d_in[7];
    float* out = (float*)d_out;
    const int n_atoms = in_sizes[1];

    prep<<<dim3(64, 2), 256>>>(W1, W2, batch, out);

    cudaFuncSetAttribute(fused_mlp, cudaFuncAttributeMaxDynamicSharedMemorySize, SMEM_BYTES);
    int ntiles = (n_atoms + TM - 1) / TM;
    int grid = ntiles < NCTA ? ntiles : NCTA;
    fused_mlp<<<grid, NTHREADS, SMEM_BYTES>>>(atom_node, batch, b1, b2, W3, b3, out, n_atoms);
}